// round 1
// baseline (speedup 1.0000x reference)
#include <cuda_runtime.h>
#include <math.h>

#define C_DIM 256
#define NROI  512
#define NBIN  49

// NHWC scratch for all 4 pyramid levels:
// lvl0: 2*256*256*256, lvl1: 2*128*128*256, lvl2: 2*64*64*256, lvl3: 2*32*32*256
// total = 44,564,480 floats (178 MB)
__device__ float g_nhwc[44564480];

// -------------------------------------------------------------------------
// NCHW -> NHWC transpose, one level per launch. [B, C, HW] -> [B, HW, C]
// -------------------------------------------------------------------------
__global__ __launch_bounds__(256) void k_transpose(const float* __restrict__ in, int lvl) {
    __shared__ float tile[32][33];
    const int Hs = 256 >> lvl;
    const int HW = Hs * Hs;
    const size_t base = (lvl == 0) ? 0ul
                      : (lvl == 1) ? 33554432ul
                      : (lvl == 2) ? 41943040ul
                      :              44040192ul;

    const int hw0 = blockIdx.x * 32;
    const int c0  = blockIdx.y * 32;
    const int b   = blockIdx.z;

    const float* __restrict__ ip = in + (size_t)b * C_DIM * HW;
    float* __restrict__ op = g_nhwc + base + (size_t)b * HW * C_DIM;

    const int tx = threadIdx.x, ty = threadIdx.y;

#pragma unroll
    for (int i = 0; i < 32; i += 8)
        tile[ty + i][tx] = ip[(size_t)(c0 + ty + i) * HW + (hw0 + tx)];
    __syncthreads();
#pragma unroll
    for (int i = 0; i < 32; i += 8)
        op[(size_t)(hw0 + ty + i) * C_DIM + (c0 + tx)] = tile[tx][ty + i];
}

// -------------------------------------------------------------------------
// ROIAlign gather from NHWC scratch. One block per ROI, 256 threads.
// Phase A: 196 sample descriptors (4 corner offsets + 4 weights*0.25) in smem.
// Phase B: 2 chunks of 128 channels; lanes = float4 channel groups (coalesced
//          512B corner loads); results staged in smem, written out contiguous.
// -------------------------------------------------------------------------
__global__ __launch_bounds__(256) void k_gather(const float* __restrict__ boxes,
                                                float* __restrict__ out) {
    __shared__ int   s_o[196][4];
    __shared__ float s_w[196][4];
    __shared__ float s_out[NBIN * 132];   // 128 channels + 4 pad per bin

    const int tid = threadIdx.x;
    const int roi = blockIdx.x;
    const int b   = roi >> 8;             // N = 256 boxes per batch

    const float bx1 = __ldg(boxes + roi * 4 + 0);
    const float by1 = __ldg(boxes + roi * 4 + 1);
    const float bx2 = __ldg(boxes + roi * 4 + 2);
    const float by2 = __ldg(boxes + roi * 4 + 3);

    // FPN level selection (matches reference fp32 math)
    const float size = sqrtf((bx2 - bx1) * (by2 - by1));
    int lvl = (int)floorf(4.0f + log2f(size / 224.0f + 1e-8f));
    lvl = max(2, min(5, lvl)) - 2;

    const int   H     = 256 >> lvl;
    const float scale = 0.25f / (float)(1 << lvl);
    const size_t base_off = ((lvl == 0) ? 0ul
                           : (lvl == 1) ? 33554432ul
                           : (lvl == 2) ? 41943040ul
                           :              44040192ul)
                          + (size_t)b * H * H * C_DIM;
    const float* __restrict__ fb = g_nhwc + base_off;

    const float x1s = bx1 * scale - 0.5f;
    const float y1s = by1 * scale - 0.5f;
    const float bw  = ((bx2 * scale - 0.5f) - x1s) * (1.0f / 7.0f);
    const float bh  = ((by2 * scale - 0.5f) - y1s) * (1.0f / 7.0f);

    if (tid < 196) {
        const int iy = tid / 14;
        const int ix = tid - iy * 14;
        const float ys = y1s + ((float)iy + 0.5f) * 0.5f * bh;
        const float xs = x1s + ((float)ix + 0.5f) * 0.5f * bw;
        const bool valid = (ys >= -1.0f) && (ys <= (float)H) &&
                           (xs >= -1.0f) && (xs <= (float)H);
        const float yc = fminf(fmaxf(ys, 0.0f), (float)(H - 1));
        const float xc = fminf(fmaxf(xs, 0.0f), (float)(H - 1));
        const int y0  = (int)floorf(yc);
        const int x0  = (int)floorf(xc);
        const int y1i = min(y0 + 1, H - 1);
        const int x1i = min(x0 + 1, H - 1);
        const float ly = yc - (float)y0, hy = 1.0f - ly;
        const float lx = xc - (float)x0, hx = 1.0f - lx;
        const float m = valid ? 0.25f : 0.0f;   // fold 2x2-sample mean here
        s_w[tid][0] = hy * hx * m;
        s_w[tid][1] = hy * lx * m;
        s_w[tid][2] = ly * hx * m;
        s_w[tid][3] = ly * lx * m;
        const int r0 = y0 * H, r1 = y1i * H;
        s_o[tid][0] = (r0 + x0)  * C_DIM;
        s_o[tid][1] = (r0 + x1i) * C_DIM;
        s_o[tid][2] = (r1 + x0)  * C_DIM;
        s_o[tid][3] = (r1 + x1i) * C_DIM;
    }
    __syncthreads();

    float* __restrict__ outroi = out + (size_t)roi * (C_DIM * NBIN);

#pragma unroll
    for (int chunk = 0; chunk < 2; chunk++) {
        const int c0 = chunk << 7;  // 0, 128
        for (int t = tid; t < NBIN * 32; t += 256) {
            const int bin = t >> 5;               // same for all lanes of a warp
            const int cl  = (t & 31) << 2;        // 0..124, lanes contiguous
            const int c   = c0 + cl;
            const int ph  = bin / 7;
            const int pw  = bin - ph * 7;
            float ax = 0.f, ay = 0.f, az = 0.f, aw = 0.f;
#pragma unroll
            for (int sy = 0; sy < 2; sy++) {
#pragma unroll
                for (int sx = 0; sx < 2; sx++) {
                    const int s = (ph * 2 + sy) * 14 + (pw * 2 + sx);
                    const float w0 = s_w[s][0], w1 = s_w[s][1];
                    const float w2 = s_w[s][2], w3 = s_w[s][3];
                    const float4 v0 = *(const float4*)(fb + s_o[s][0] + c);
                    const float4 v1 = *(const float4*)(fb + s_o[s][1] + c);
                    const float4 v2 = *(const float4*)(fb + s_o[s][2] + c);
                    const float4 v3 = *(const float4*)(fb + s_o[s][3] + c);
                    ax += w0 * v0.x + w1 * v1.x + w2 * v2.x + w3 * v3.x;
                    ay += w0 * v0.y + w1 * v1.y + w2 * v2.y + w3 * v3.y;
                    az += w0 * v0.z + w1 * v1.z + w2 * v2.z + w3 * v3.z;
                    aw += w0 * v0.w + w1 * v1.w + w2 * v2.w + w3 * v3.w;
                }
            }
            *(float4*)(&s_out[bin * 132 + cl]) = make_float4(ax, ay, az, aw);
        }
        __syncthreads();
        // Write chunk region [c0..c0+127][49] — contiguous & coalesced
        float* __restrict__ og = outroi + c0 * NBIN;
        for (int e = tid; e < 128 * NBIN; e += 256) {
            const int cl  = e / NBIN;
            const int bin = e - cl * NBIN;
            og[e] = s_out[bin * 132 + cl];
        }
        __syncthreads();
    }
}

// -------------------------------------------------------------------------
extern "C" void kernel_launch(void* const* d_in, const int* in_sizes, int n_in,
                              void* d_out, int out_size) {
    const float* feats[4] = {
        (const float*)d_in[0],   // x2  [2,256,256,256]
        (const float*)d_in[1],   // x3  [2,256,128,128]
        (const float*)d_in[2],   // x4  [2,256, 64, 64]
        (const float*)d_in[3],   // x5  [2,256, 32, 32]
    };
    const float* boxes = (const float*)d_in[4];   // [2,256,4]
    float* out = (float*)d_out;                   // [512,256,7,7]

    for (int l = 0; l < 4; l++) {
        const int Hs = 256 >> l;
        const int HW = Hs * Hs;
        dim3 grid(HW / 32, C_DIM / 32, 2);
        dim3 block(32, 8);
        k_transpose<<<grid, block>>>(feats[l], l);
    }
    k_gather<<<NROI, 256>>>(boxes, out);
}

// round 2
// speedup vs baseline: 1.0931x; 1.0931x over previous
#include <cuda_runtime.h>
#include <cuda_fp16.h>
#include <math.h>

#define C_DIM 256
#define NROI  512
#define NBIN  49

// NHWC fp16 scratch for all 4 pyramid levels (element offsets):
// lvl0: 2*256*256*256 = 33,554,432
// lvl1: 2*256*128*128 =  8,388,608  (base 33,554,432)
// lvl2: 2*256*64*64   =  2,097,152  (base 41,943,040)
// lvl3: 2*256*32*32   =    524,288  (base 44,040,192)
__device__ __half g_nhwc[44564480];

// -------------------------------------------------------------------------
// Fused NCHW -> NHWC(fp16) transpose for all 4 levels in one launch.
// 64c x 64hw tiles; float4 loads, half2 stores (both sides 128B/warp).
// Block counts: lvl0 8192, lvl1 2048, lvl2 512, lvl3 128  (total 10880)
// -------------------------------------------------------------------------
__global__ __launch_bounds__(256) void k_transpose(const float* __restrict__ p0,
                                                   const float* __restrict__ p1,
                                                   const float* __restrict__ p2,
                                                   const float* __restrict__ p3) {
    __shared__ float tile[64][65];

    int bid = blockIdx.x;
    int lvl;
    const float* __restrict__ in;
    size_t base;
    if (bid < 8192)       { lvl = 0; in = p0; base = 0ul; }
    else if (bid < 10240) { lvl = 1; in = p1; base = 33554432ul; bid -= 8192; }
    else if (bid < 10752) { lvl = 2; in = p2; base = 41943040ul; bid -= 10240; }
    else                  { lvl = 3; in = p3; base = 44040192ul; bid -= 10752; }

    const int Hs = 256 >> lvl;
    const int HW = Hs * Hs;
    const int hwTiles = HW >> 6;

    const int hwTile = bid % hwTiles;
    const int rest   = bid / hwTiles;
    const int cTile  = rest & 3;
    const int b      = rest >> 2;

    const int hw0 = hwTile << 6;
    const int c0  = cTile << 6;

    const int t  = threadIdx.x;
    const int tx = t & 15;    // hw group (float4)
    const int ty = t >> 4;    // c 0..15

    const float* __restrict__ ip =
        in + (size_t)b * C_DIM * HW + (size_t)c0 * HW + hw0;

#pragma unroll
    for (int k = 0; k < 4; k++) {
        const int c = ty + 16 * k;
        const float4 v = *(const float4*)(ip + (size_t)c * HW + 4 * tx);
        tile[c][4 * tx + 0] = v.x;
        tile[c][4 * tx + 1] = v.y;
        tile[c][4 * tx + 2] = v.z;
        tile[c][4 * tx + 3] = v.w;
    }
    __syncthreads();

    __half* __restrict__ op =
        g_nhwc + base + (size_t)b * HW * C_DIM + (size_t)hw0 * C_DIM + c0;

    const int c2 = t & 31;    // half2 channel-pair lane
    const int r0 = t >> 5;    // 8 row groups
#pragma unroll
    for (int k = 0; k < 8; k++) {
        const int row = r0 + 8 * k;
        const float a = tile[2 * c2 + 0][row];
        const float bfv = tile[2 * c2 + 1][row];
        ((half2*)(op + (size_t)row * C_DIM))[c2] = __floats2half2_rn(a, bfv);
    }
}

// -------------------------------------------------------------------------
// ROIAlign gather from fp16 NHWC scratch. One block per ROI, 256 threads.
// -------------------------------------------------------------------------
__global__ __launch_bounds__(256) void k_gather(const float* __restrict__ boxes,
                                                float* __restrict__ out) {
    __shared__ int   s_o[196][4];
    __shared__ float s_w[196][4];
    __shared__ float s_out[NBIN * 132];   // 128 channels + 4 pad per bin

    const int tid = threadIdx.x;
    const int roi = blockIdx.x;
    const int b   = roi >> 8;             // N = 256 boxes per batch

    const float bx1 = __ldg(boxes + roi * 4 + 0);
    const float by1 = __ldg(boxes + roi * 4 + 1);
    const float bx2 = __ldg(boxes + roi * 4 + 2);
    const float by2 = __ldg(boxes + roi * 4 + 3);

    // FPN level selection (matches reference fp32 math)
    const float size = sqrtf((bx2 - bx1) * (by2 - by1));
    int lvl = (int)floorf(4.0f + log2f(size / 224.0f + 1e-8f));
    lvl = max(2, min(5, lvl)) - 2;

    const int   H     = 256 >> lvl;
    const float scale = 0.25f / (float)(1 << lvl);
    const size_t base_off = ((lvl == 0) ? 0ul
                           : (lvl == 1) ? 33554432ul
                           : (lvl == 2) ? 41943040ul
                           :              44040192ul)
                          + (size_t)b * H * H * C_DIM;
    const __half* __restrict__ fb = g_nhwc + base_off;

    const float x1s = bx1 * scale - 0.5f;
    const float y1s = by1 * scale - 0.5f;
    const float bw  = ((bx2 * scale - 0.5f) - x1s) * (1.0f / 7.0f);
    const float bh  = ((by2 * scale - 0.5f) - y1s) * (1.0f / 7.0f);

    if (tid < 196) {
        const int iy = tid / 14;
        const int ix = tid - iy * 14;
        const float ys = y1s + ((float)iy + 0.5f) * 0.5f * bh;
        const float xs = x1s + ((float)ix + 0.5f) * 0.5f * bw;
        const bool valid = (ys >= -1.0f) && (ys <= (float)H) &&
                           (xs >= -1.0f) && (xs <= (float)H);
        const float yc = fminf(fmaxf(ys, 0.0f), (float)(H - 1));
        const float xc = fminf(fmaxf(xs, 0.0f), (float)(H - 1));
        const int y0  = (int)floorf(yc);
        const int x0  = (int)floorf(xc);
        const int y1i = min(y0 + 1, H - 1);
        const int x1i = min(x0 + 1, H - 1);
        const float ly = yc - (float)y0, hy = 1.0f - ly;
        const float lx = xc - (float)x0, hx = 1.0f - lx;
        const float m = valid ? 0.25f : 0.0f;   // fold 2x2-sample mean here
        s_w[tid][0] = hy * hx * m;
        s_w[tid][1] = hy * lx * m;
        s_w[tid][2] = ly * hx * m;
        s_w[tid][3] = ly * lx * m;
        const int r0 = y0 * H, r1 = y1i * H;
        s_o[tid][0] = (r0 + x0)  * C_DIM;
        s_o[tid][1] = (r0 + x1i) * C_DIM;
        s_o[tid][2] = (r1 + x0)  * C_DIM;
        s_o[tid][3] = (r1 + x1i) * C_DIM;
    }
    __syncthreads();

    float* __restrict__ outroi = out + (size_t)roi * (C_DIM * NBIN);

#pragma unroll
    for (int chunk = 0; chunk < 2; chunk++) {
        const int c0 = chunk << 7;  // 0, 128
        for (int t = tid; t < NBIN * 32; t += 256) {
            const int bin = t >> 5;               // same for all lanes of a warp
            const int cl  = (t & 31) << 2;        // 0..124, lanes contiguous
            const int c   = c0 + cl;
            const int ph  = bin / 7;
            const int pw  = bin - ph * 7;
            float ax = 0.f, ay = 0.f, az = 0.f, aw = 0.f;
#pragma unroll
            for (int sy = 0; sy < 2; sy++) {
#pragma unroll
                for (int sx = 0; sx < 2; sx++) {
                    const int s = (ph * 2 + sy) * 14 + (pw * 2 + sx);
                    const float w0 = s_w[s][0], w1 = s_w[s][1];
                    const float w2 = s_w[s][2], w3 = s_w[s][3];
                    const uint2 r0 = *(const uint2*)(fb + s_o[s][0] + c);
                    const uint2 r1 = *(const uint2*)(fb + s_o[s][1] + c);
                    const uint2 r2 = *(const uint2*)(fb + s_o[s][2] + c);
                    const uint2 r3 = *(const uint2*)(fb + s_o[s][3] + c);
                    const float2 a0 = __half22float2(*(const half2*)&r0.x);
                    const float2 b0 = __half22float2(*(const half2*)&r0.y);
                    const float2 a1 = __half22float2(*(const half2*)&r1.x);
                    const float2 b1 = __half22float2(*(const half2*)&r1.y);
                    const float2 a2 = __half22float2(*(const half2*)&r2.x);
                    const float2 b2 = __half22float2(*(const half2*)&r2.y);
                    const float2 a3 = __half22float2(*(const half2*)&r3.x);
                    const float2 b3 = __half22float2(*(const half2*)&r3.y);
                    ax += w0 * a0.x + w1 * a1.x + w2 * a2.x + w3 * a3.x;
                    ay += w0 * a0.y + w1 * a1.y + w2 * a2.y + w3 * a3.y;
                    az += w0 * b0.x + w1 * b1.x + w2 * b2.x + w3 * b3.x;
                    aw += w0 * b0.y + w1 * b1.y + w2 * b2.y + w3 * b3.y;
                }
            }
            *(float4*)(&s_out[bin * 132 + cl]) = make_float4(ax, ay, az, aw);
        }
        __syncthreads();
        // Write chunk region [c0..c0+127][49] — contiguous & coalesced
        float* __restrict__ og = outroi + c0 * NBIN;
        for (int e = tid; e < 128 * NBIN; e += 256) {
            const int cl  = e / NBIN;
            const int bin = e - cl * NBIN;
            og[e] = s_out[bin * 132 + cl];
        }
        __syncthreads();
    }
}

// -------------------------------------------------------------------------
extern "C" void kernel_launch(void* const* d_in, const int* in_sizes, int n_in,
                              void* d_out, int out_size) {
    const float* x2 = (const float*)d_in[0];   // [2,256,256,256]
    const float* x3 = (const float*)d_in[1];   // [2,256,128,128]
    const float* x4 = (const float*)d_in[2];   // [2,256, 64, 64]
    const float* x5 = (const float*)d_in[3];   // [2,256, 32, 32]
    const float* boxes = (const float*)d_in[4];// [2,256,4]
    float* out = (float*)d_out;                // [512,256,7,7]

    k_transpose<<<10880, 256>>>(x2, x3, x4, x5);
    k_gather<<<NROI, 256>>>(boxes, out);
}

// round 4
// speedup vs baseline: 1.5862x; 1.4511x over previous
#include <cuda_runtime.h>
#include <cuda_fp16.h>
#include <math.h>

#define C_DIM 256
#define NROI  512
#define NBIN  49

// NHWC fp16 scratch, 4 levels (element offsets):
// lvl0 base 0 (2*256*256*256), lvl1 base 33554432, lvl2 base 41943040, lvl3 base 44040192
__device__ __half g_nhwc[44564480];

// -------------------------------------------------------------------------
// Fused NCHW -> NHWC(fp16) transpose, all 4 levels, one launch.
// 64c x 64hw tiles; float4 streaming loads (__ldcs), half2 stores.
// -------------------------------------------------------------------------
__global__ __launch_bounds__(256) void k_transpose(const float* __restrict__ p0,
                                                   const float* __restrict__ p1,
                                                   const float* __restrict__ p2,
                                                   const float* __restrict__ p3) {
    __shared__ float tile[64][65];

    int bid = blockIdx.x;
    int lvl;
    const float* __restrict__ in;
    size_t base;
    if (bid < 8192)       { lvl = 0; in = p0; base = 0ul; }
    else if (bid < 10240) { lvl = 1; in = p1; base = 33554432ul; bid -= 8192; }
    else if (bid < 10752) { lvl = 2; in = p2; base = 41943040ul; bid -= 10240; }
    else                  { lvl = 3; in = p3; base = 44040192ul; bid -= 10752; }

    const int Hs = 256 >> lvl;
    const int HW = Hs * Hs;
    const int hwTiles = HW >> 6;

    const int hwTile = bid % hwTiles;
    const int rest   = bid / hwTiles;
    const int cTile  = rest & 3;
    const int b      = rest >> 2;

    const int hw0 = hwTile << 6;
    const int c0  = cTile << 6;

    const int t  = threadIdx.x;
    const int tx = t & 15;    // hw group (float4)
    const int ty = t >> 4;    // c 0..15

    const float* __restrict__ ip =
        in + (size_t)b * C_DIM * HW + (size_t)c0 * HW + hw0;

#pragma unroll
    for (int k = 0; k < 4; k++) {
        const int c = ty + 16 * k;
        const float4 v = __ldcs((const float4*)(ip + (size_t)c * HW + 4 * tx));
        tile[c][4 * tx + 0] = v.x;
        tile[c][4 * tx + 1] = v.y;
        tile[c][4 * tx + 2] = v.z;
        tile[c][4 * tx + 3] = v.w;
    }
    __syncthreads();

    __half* __restrict__ op =
        g_nhwc + base + (size_t)b * HW * C_DIM + (size_t)hw0 * C_DIM + c0;

    const int c2 = t & 31;    // half2 channel-pair lane
    const int r0 = t >> 5;    // 8 row groups
#pragma unroll
    for (int k = 0; k < 8; k++) {
        const int row = r0 + 8 * k;
        const float a = tile[2 * c2 + 0][row];
        const float bfv = tile[2 * c2 + 1][row];
        ((half2*)(op + (size_t)row * C_DIM))[c2] = __floats2half2_rn(a, bfv);
    }
}

// -------------------------------------------------------------------------
// ROIAlign gather. Grid (512 rois, 4 chunks); each block does 64 channels.
// 256 threads = 8 warps; warp w handles bins w, w+8, ...; lane = half2 pair.
// -------------------------------------------------------------------------
__global__ __launch_bounds__(256) void k_gather(const float* __restrict__ boxes,
                                                float* __restrict__ out) {
    __shared__ int   s_o[196][4];
    __shared__ float s_w[196][4];
    __shared__ float s_out[NBIN * 66];    // [bin][64ch], pitch 66 (EVEN: float2-safe)

    const int tid = threadIdx.x;
    const int roi = blockIdx.x;
    const int c0  = blockIdx.y << 6;      // 0,64,128,192
    const int b   = roi >> 8;             // N = 256 boxes per batch

    const float bx1 = __ldg(boxes + roi * 4 + 0);
    const float by1 = __ldg(boxes + roi * 4 + 1);
    const float bx2 = __ldg(boxes + roi * 4 + 2);
    const float by2 = __ldg(boxes + roi * 4 + 3);

    const float size = sqrtf((bx2 - bx1) * (by2 - by1));
    int lvl = (int)floorf(4.0f + log2f(size / 224.0f + 1e-8f));
    lvl = max(2, min(5, lvl)) - 2;

    const int   H     = 256 >> lvl;
    const float scale = 0.25f / (float)(1 << lvl);
    const size_t base_off = ((lvl == 0) ? 0ul
                           : (lvl == 1) ? 33554432ul
                           : (lvl == 2) ? 41943040ul
                           :              44040192ul)
                          + (size_t)b * H * H * C_DIM;
    const __half* __restrict__ fb = g_nhwc + base_off + c0;

    const float x1s = bx1 * scale - 0.5f;
    const float y1s = by1 * scale - 0.5f;
    const float bw  = ((bx2 * scale - 0.5f) - x1s) * (1.0f / 7.0f);
    const float bh  = ((by2 * scale - 0.5f) - y1s) * (1.0f / 7.0f);

    if (tid < 196) {
        const int iy = tid / 14;
        const int ix = tid - iy * 14;
        const float ys = y1s + ((float)iy + 0.5f) * 0.5f * bh;
        const float xs = x1s + ((float)ix + 0.5f) * 0.5f * bw;
        const bool valid = (ys >= -1.0f) && (ys <= (float)H) &&
                           (xs >= -1.0f) && (xs <= (float)H);
        const float yc = fminf(fmaxf(ys, 0.0f), (float)(H - 1));
        const float xc = fminf(fmaxf(xs, 0.0f), (float)(H - 1));
        const int y0  = (int)floorf(yc);
        const int x0  = (int)floorf(xc);
        const int y1i = min(y0 + 1, H - 1);
        const int x1i = min(x0 + 1, H - 1);
        const float ly = yc - (float)y0, hy = 1.0f - ly;
        const float lx = xc - (float)x0, hx = 1.0f - lx;
        const float m = valid ? 0.25f : 0.0f;   // fold 2x2 mean
        s_w[tid][0] = hy * hx * m;
        s_w[tid][1] = hy * lx * m;
        s_w[tid][2] = ly * hx * m;
        s_w[tid][3] = ly * lx * m;
        const int r0 = y0 * H, r1 = y1i * H;
        s_o[tid][0] = (r0 + x0)  * C_DIM;
        s_o[tid][1] = (r0 + x1i) * C_DIM;
        s_o[tid][2] = (r1 + x0)  * C_DIM;
        s_o[tid][3] = (r1 + x1i) * C_DIM;
    }
    __syncthreads();

    const int warp = tid >> 5;
    const int lane = tid & 31;
    const int cl   = lane << 1;           // channel pair within 64-ch chunk

    for (int bin = warp; bin < NBIN; bin += 8) {
        const int ph = bin / 7;
        const int pw = bin - ph * 7;
        float ax = 0.f, ay = 0.f;
#pragma unroll
        for (int sy = 0; sy < 2; sy++) {
#pragma unroll
            for (int sx = 0; sx < 2; sx++) {
                const int s = (ph * 2 + sy) * 14 + (pw * 2 + sx);
                const float w0 = s_w[s][0], w1 = s_w[s][1];
                const float w2 = s_w[s][2], w3 = s_w[s][3];
                const float2 v0 = __half22float2(*(const half2*)(fb + s_o[s][0] + cl));
                const float2 v1 = __half22float2(*(const half2*)(fb + s_o[s][1] + cl));
                const float2 v2 = __half22float2(*(const half2*)(fb + s_o[s][2] + cl));
                const float2 v3 = __half22float2(*(const half2*)(fb + s_o[s][3] + cl));
                ax += w0 * v0.x + w1 * v1.x + w2 * v2.x + w3 * v3.x;
                ay += w0 * v0.y + w1 * v1.y + w2 * v2.y + w3 * v3.y;
            }
        }
        *(float2*)(&s_out[bin * 66 + cl]) = make_float2(ax, ay);
    }
    __syncthreads();

    // Write [c0..c0+63][49] region — contiguous 3136 floats, coalesced.
    float* __restrict__ og = out + (size_t)roi * (C_DIM * NBIN) + (size_t)c0 * NBIN;
    for (int e = tid; e < 64 * NBIN; e += 256) {
        const int ch  = e / NBIN;
        const int bin = e - ch * NBIN;
        og[e] = s_out[bin * 66 + ch];
    }
}

// -------------------------------------------------------------------------
extern "C" void kernel_launch(void* const* d_in, const int* in_sizes, int n_in,
                              void* d_out, int out_size) {
    const float* x2 = (const float*)d_in[0];   // [2,256,256,256]
    const float* x3 = (const float*)d_in[1];   // [2,256,128,128]
    const float* x4 = (const float*)d_in[2];   // [2,256, 64, 64]
    const float* x5 = (const float*)d_in[3];   // [2,256, 32, 32]
    const float* boxes = (const float*)d_in[4];// [2,256,4]
    float* out = (float*)d_out;                // [512,256,7,7]

    k_transpose<<<10880, 256>>>(x2, x3, x4, x5);
    dim3 ggrid(NROI, 4);
    k_gather<<<ggrid, 256>>>(boxes, out);
}